// round 15
// baseline (speedup 1.0000x reference)
#include <cuda_runtime.h>
#include <cuda_bf16.h>
#include <math.h>
#include <stdint.h>

// ---------------- problem shapes ----------------
#define NQ 2048
#define NS 64
#define LL 8
#define DD 576
#define QF (NQ * LL)   // 16384 query frames
#define SF (NS * LL)   // 512 support frames
#define EPSILON 0.01f

// ---------------- GEMM tiling ----------------
#define M_TILE 128
#define N_TILE 128
#define KC 64                                // bf16 K-elems per chunk: 128B rows
#define NCHUNK (DD / KC)                     // 9
#define NSTAGE 3
#define A_STAGE (M_TILE * 128)               // 16384
#define B_STAGE (N_TILE * 128)               // 16384
#define STAGE_BYTES (A_STAGE + B_STAGE)      // 32768
#define SMEM_NORMS 1024
#define DSTRIDE 132                          // dist row stride (floats, 16B-aligned)
#define SMEM_TOTAL (SMEM_NORMS + NSTAGE * STAGE_BYTES)  // 99328; x2 = 198656

#define NTHREADS 256                         // 8 warps, each 64x32 warp tile

// ---------------- scratch (device globals) ----------------
__device__ __nv_bfloat16 g_Qh[(size_t)QF * DD];
__device__ __nv_bfloat16 g_Sh[(size_t)SF * DD];
__device__ float g_qn[QF];
__device__ float g_sn[SF];

// ---------------- PTX helpers ----------------
__device__ __forceinline__ uint32_t smem_u32(const void* p) {
    uint32_t a;
    asm("{ .reg .u64 t; cvta.to.shared.u64 t, %1; cvt.u32.u64 %0, t; }"
        : "=r"(a) : "l"(p));
    return a;
}
__device__ __forceinline__ void cp16(uint32_t saddr, const void* gptr) {
    asm volatile("cp.async.cg.shared.global [%0], [%1], 16;"
                 :: "r"(saddr), "l"(gptr) : "memory");
}
#define CP_COMMIT() asm volatile("cp.async.commit_group;" ::: "memory")
#define CP_WAIT(n)  asm volatile("cp.async.wait_group %0;" :: "n"(n) : "memory")

__device__ __forceinline__ uint32_t pack_bf16x2(float lo, float hi) {
    uint32_t r;
    asm("cvt.rn.bf16x2.f32 %0, %1, %2;" : "=r"(r) : "f"(hi), "f"(lo));
    return r;
}
__device__ __forceinline__ void ldsm4(uint32_t r[4], uint32_t addr) {
    asm volatile("ldmatrix.sync.aligned.m8n8.x4.shared.b16 {%0,%1,%2,%3}, [%4];"
                 : "=r"(r[0]), "=r"(r[1]), "=r"(r[2]), "=r"(r[3]) : "r"(addr));
}
__device__ __forceinline__ void mma16816(float c[4], const uint32_t a[4],
                                         uint32_t b0, uint32_t b1) {
    asm volatile(
        "mma.sync.aligned.m16n8k16.row.col.f32.bf16.bf16.f32 "
        "{%0,%1,%2,%3}, {%4,%5,%6,%7}, {%8,%9}, {%0,%1,%2,%3};"
        : "+f"(c[0]), "+f"(c[1]), "+f"(c[2]), "+f"(c[3])
        : "r"(a[0]), "r"(a[1]), "r"(a[2]), "r"(a[3]), "r"(b0), "r"(b1));
}
__device__ __forceinline__ uint32_t sw128(uint32_t off) {
    return off ^ ((off >> 3) & 0x70);
}
__device__ __forceinline__ float ex2f(float x) {
    float y; asm("ex2.approx.ftz.f32 %0, %1;" : "=f"(y) : "f"(x)); return y;
}
__device__ __forceinline__ float lg2f(float x) {
    float y; asm("lg2.approx.ftz.f32 %0, %1;" : "=f"(y) : "f"(x)); return y;
}

// ================= convert (f32 -> bf16) + norms =================
__global__ __launch_bounds__(256) void convert_kernel(const float* __restrict__ Q,
                                                      const float* __restrict__ S) {
    int w = (blockIdx.x * blockDim.x + threadIdx.x) >> 5;
    int lane = threadIdx.x & 31;
    if (w >= QF + SF) return;
    bool isQ = (w < QF);
    int r = isQ ? w : (w - QF);
    const float4* src = (const float4*)((isQ ? Q : S) + (size_t)r * DD);  // 144/row
    uint2* dst = (uint2*)((isQ ? g_Qh : g_Sh) + (size_t)r * DD);
    float s = 0.f;
#pragma unroll
    for (int j = 0; j < 4; j++) {
        int k = lane + 32 * j;
        float4 v = src[k];
        s = fmaf(v.x, v.x, fmaf(v.y, v.y, fmaf(v.z, v.z, fmaf(v.w, v.w, s))));
        uint2 o;
        o.x = pack_bf16x2(v.x, v.y);
        o.y = pack_bf16x2(v.z, v.w);
        dst[k] = o;
    }
    if (lane < 16) {
        int k = 128 + lane;
        float4 v = src[k];
        s = fmaf(v.x, v.x, fmaf(v.y, v.y, fmaf(v.z, v.z, fmaf(v.w, v.w, s))));
        uint2 o;
        o.x = pack_bf16x2(v.x, v.y);
        o.y = pack_bf16x2(v.z, v.w);
        dst[k] = o;
    }
#pragma unroll
    for (int o = 16; o > 0; o >>= 1) s += __shfl_down_sync(0xffffffffu, s, o);
    if (lane == 0) {
        float n = sqrtf(s);
        if (isQ) g_qn[r] = n;
        else     g_sn[r] = n;
    }
}

// ================= softmins (lbda = 0.5) =================
#define CEXP 2.885390081777927f   // 2/ln2
#define CLOG 0.346573590279973f   // 0.5*ln2
__device__ __forceinline__ float softmin2(float a, float b) {
    float m = fminf(a, b), x = fmaxf(a, b);
    float s = 1.f + ex2f(CEXP * (m - x));
    return fmaf(-CLOG, lg2f(s), m);
}
__device__ __forceinline__ float softmin3(float a, float b, float c) {
    float m = fminf(fminf(a, b), c);
    float x = fmaxf(fmaxf(a, b), c);
    float mid = ((a + b) + c) - m - x;
    float s = 1.f + ex2f(CEXP * (m - mid)) + ex2f(CEXP * (m - x));
    return fmaf(-CLOG, lg2f(s), m);
}

// ================= fused GEMM + epilogue + DP =================
struct Frags { uint32_t a[4][4]; uint32_t b[2][4]; };   // 24 regs

__device__ __forceinline__ void load_frags(Frags& f, uint32_t Ab, uint32_t Bb,
                                           int ks, int wm, int wn, int lane) {
#pragma unroll
    for (int fm = 0; fm < 4; fm++) {
        int row = wm * 64 + fm * 16 + (lane & 15);
        uint32_t off = row * 128 + ks * 32 + ((lane >> 4) & 1) * 16;
        ldsm4(f.a[fm], Ab + sw128(off));
    }
#pragma unroll
    for (int p = 0; p < 2; p++) {
        int n = wn * 32 + p * 16 + (lane & 7) + ((lane >> 4) & 1) * 8;
        uint32_t off = n * 128 + ks * 32 + ((lane >> 3) & 1) * 16;
        ldsm4(f.b[p], Bb + sw128(off));
    }
}
__device__ __forceinline__ void mma_frags(float acc[4][4][4], const Frags& f) {
#pragma unroll
    for (int fm = 0; fm < 4; fm++) {
        mma16816(acc[fm][0], f.a[fm], f.b[0][0], f.b[0][1]);
        mma16816(acc[fm][1], f.a[fm], f.b[0][2], f.b[0][3]);
        mma16816(acc[fm][2], f.a[fm], f.b[1][0], f.b[1][1]);
        mma16816(acc[fm][3], f.a[fm], f.b[1][2], f.b[1][3]);
    }
}

// 2048 x 16B vectors per chunk (A 1024 + B 1024); 8 per thread, coalesced:
// 8 consecutive threads cover one contiguous 128B row.
__device__ __forceinline__ void issue_chunk(uint32_t stg, int stage, int c,
                                            const char* qsrc, const char* ssrc,
                                            int tid) {
#pragma unroll
    for (int i = 0; i < 8; i++) {
        int idx = tid + i * NTHREADS;       // 0..2047
        bool isA = idx < 1024;
        int j = idx & 1023;
        int r = j >> 3, v = j & 7;
        uint32_t dst = stg + stage * STAGE_BYTES + (isA ? 0 : A_STAGE) +
                       sw128(r * 128 + v * 16);
        const char* src = (isA ? qsrc : ssrc) +
                          (size_t)r * (DD * 2) + c * (KC * 2) + v * 16;
        cp16(dst, src);
    }
    CP_COMMIT();
}

__global__ __launch_bounds__(NTHREADS, 2) void fused_kernel(float* __restrict__ out) {
    extern __shared__ char smem[];
    const uint32_t sb = smem_u32(smem);
    float* sqn = (float*)smem;            // [128]
    float* ssn = (float*)(smem + 512);    // [128]
    const uint32_t stg = sb + SMEM_NORMS;
    const int tid = threadIdx.x;
    const int wid = tid >> 5;
    const int lane = tid & 31;
    const int bcol = blockIdx.x * N_TILE;
    const int brow = blockIdx.y * M_TILE;

    if (tid < 128) sqn[tid] = g_qn[brow + tid];
    else           ssn[tid - 128] = g_sn[bcol + tid - 128];

    const char* qsrc = (const char*)(g_Qh + (size_t)brow * DD);
    const char* ssrc = (const char*)(g_Sh + (size_t)bcol * DD);

    const int wm = wid & 1;    // 2 m-groups of 64 rows
    const int wn = wid >> 1;   // 4 n-groups of 32 cols

    float acc[4][4][4];
#pragma unroll
    for (int i = 0; i < 4; i++)
#pragma unroll
        for (int j = 0; j < 4; j++)
#pragma unroll
            for (int k = 0; k < 4; k++) acc[i][j][k] = 0.f;

    issue_chunk(stg, 0, 0, qsrc, ssrc, tid);
    issue_chunk(stg, 1, 1, qsrc, ssrc, tid);

    Frags fr[2];
#pragma unroll 1
    for (int c = 0; c < NCHUNK; c++) {
        if (c < NCHUNK - 1) CP_WAIT(1); else CP_WAIT(0);
        __syncthreads();                     // chunk c visible; compute(c-1) done
        if (c + 2 < NCHUNK)                  // stage (c+2)%3 freed at iter c-1
            issue_chunk(stg, (c + 2) % NSTAGE, c + 2, qsrc, ssrc, tid);
        const int s = c % NSTAGE;
        const uint32_t Ab = stg + s * STAGE_BYTES;
        const uint32_t Bb = Ab + A_STAGE;
        load_frags(fr[0], Ab, Bb, 0, wm, wn, lane);
#pragma unroll
        for (int ks = 0; ks < 4; ks++) {     // double-buffered fragments
            if (ks < 3) load_frags(fr[(ks + 1) & 1], Ab, Bb, ks + 1, wm, wn, lane);
            mma_frags(acc, fr[ks & 1]);
        }
    }
    __syncthreads();   // all stage reads done before dist overlay

    // ---- epilogue: normalized dists into smem [128][DSTRIDE] ----
    float* sdist = (float*)(smem + SMEM_NORMS);
    const int gid = lane >> 2;
    const int tc  = (lane & 3) * 2;
#pragma unroll
    for (int fm = 0; fm < 4; fm++) {
        int r0 = wm * 64 + fm * 16 + gid;
        float qn0 = sqn[r0], qn1 = sqn[r0 + 8];
#pragma unroll
        for (int fn = 0; fn < 4; fn++) {
            int c0 = wn * 32 + fn * 8 + tc;
            float sn0 = ssn[c0], sn1 = ssn[c0 + 1];
            float* a = acc[fm][fn];
            float2 v0 = make_float2(1.f - __fdividef(a[0], fmaf(qn0, sn0, EPSILON)),
                                    1.f - __fdividef(a[1], fmaf(qn0, sn1, EPSILON)));
            float2 v1 = make_float2(1.f - __fdividef(a[2], fmaf(qn1, sn0, EPSILON)),
                                    1.f - __fdividef(a[3], fmaf(qn1, sn1, EPSILON)));
            *(float2*)&sdist[r0 * DSTRIDE + c0] = v0;
            *(float2*)&sdist[(r0 + 8) * DSTRIDE + c0] = v1;
        }
    }
    __syncthreads();

    // ---- OTAM DP: 256 pairs, one thread each; forward + loop-exchanged
    // transposed DP merged in one streaming pass over the 8 dist rows ----
    {
        const int ql = tid >> 4;
        const int cl = tid & 15;
        const float* base = sdist + (ql * 8) * DSTRIDE + cl * 8;

        float F[10];   // forward DP front
        float T[8];    // transposed DP front

        float r0[8];
        {
            float4 u = *(const float4*)base;
            float4 w = *(const float4*)(base + 4);
            r0[0] = u.x; r0[1] = u.y; r0[2] = u.z; r0[3] = u.w;
            r0[4] = w.x; r0[5] = w.y; r0[6] = w.z; r0[7] = w.w;
        }
        float run = 0.f;
#pragma unroll
        for (int m = 1; m <= 8; m++) { run += r0[m - 1]; F[m] = run; }
        F[9] = run;
        T[0] = r0[0];
#pragma unroll
        for (int l = 1; l < 8; l++)
            T[l] = r0[l] + softmin3(0.f, 0.f, T[l - 1]);

#pragma unroll
        for (int j = 1; j < 8; j++) {
            float r[8];
            const float* rp = base + j * DSTRIDE;
            float4 u = *(const float4*)rp;
            float4 w = *(const float4*)(rp + 4);
            r[0] = u.x; r[1] = u.y; r[2] = u.z; r[3] = u.w;
            r[4] = w.x; r[5] = w.y; r[6] = w.z; r[7] = w.w;
            // forward row step
            float diag, left;
            {
                float nf = r[0] + softmin3(0.f, 0.f, F[1]);
                diag = F[1]; F[1] = nf; left = nf;
            }
#pragma unroll
            for (int m = 2; m <= 8; m++) {
                float nf = r[m - 1] + softmin2(diag, left);
                diag = F[m]; F[m] = nf; left = nf;
            }
            F[9] = softmin3(diag, left, F[9]);
            // transposed column step (outer index m = j+1)
            float prev_old = T[0];
            T[0] += r[0];
#pragma unroll
            for (int l = 1; l < 8; l++) {
                float cur_old = T[l];
                T[l] = r[l] + softmin2(prev_old, cur_old);
                prev_old = cur_old;
            }
        }
        {   // transposed pad step (m = 9, e = 0, include_up)
            float prev_old = T[0];
#pragma unroll
            for (int l = 1; l < 8; l++) {
                float cur_old = T[l];
                T[l] = softmin3(prev_old, cur_old, T[l - 1]);
                prev_old = cur_old;
            }
        }
        out[(blockIdx.y * 16 + ql) * NS + (blockIdx.x * 16 + cl)] = -(F[9] + T[7]);
    }
}

// ================= launch =================
extern "C" void kernel_launch(void* const* d_in, const int* in_sizes, int n_in,
                              void* d_out, int out_size) {
    const float* sup = (const float*)d_in[0];
    const float* qry = (const float*)d_in[1];
    if (n_in >= 2 && in_sizes[0] > in_sizes[1]) {
        const float* t = sup; sup = qry; qry = t;
    }
    float* out = (float*)d_out;

    {
        int warps = QF + SF;                    // 16896
        convert_kernel<<<(warps + 7) / 8, 256>>>(qry, sup);
    }
    {
        cudaFuncSetAttribute(fused_kernel,
                             cudaFuncAttributeMaxDynamicSharedMemorySize, SMEM_TOTAL);
        dim3 grid(SF / N_TILE, QF / M_TILE);    // (4, 128)
        fused_kernel<<<grid, NTHREADS, SMEM_TOTAL>>>(out);
    }
}

// round 16
// speedup vs baseline: 1.2080x; 1.2080x over previous
#include <cuda_runtime.h>
#include <cuda_bf16.h>
#include <math.h>
#include <stdint.h>

// ---------------- problem shapes ----------------
#define NQ 2048
#define NS 64
#define LL 8
#define DD 576
#define QF (NQ * LL)   // 16384 query frames
#define SF (NS * LL)   // 512 support frames
#define EPSILON 0.01f

// ---------------- GEMM tiling (R14 config) ----------------
#define M_TILE 128
#define N_TILE 64
#define KC 64                                // bf16 K-elems per chunk: 128B rows
#define NCHUNK (DD / KC)                     // 9
#define A_STAGE (M_TILE * 128)               // 16384
#define B_STAGE (N_TILE * 128)               // 8192
#define STAGE_BYTES (A_STAGE + B_STAGE)      // 24576
#define SMEM_NORMS 1024
#define DSTRIDE 68                           // dist row stride (floats, 16B-aligned)
#define SMEM_TOTAL (SMEM_NORMS + 2 * STAGE_BYTES)  // 50176; x4 CTAs = 200704

#define NTHREADS 128                         // 4 warps, each 64x32 warp tile
#define ROWB (DD * 2)                        // 1152 bytes per gmem row
#define LDSTRIDE (16 * ROWB)                 // 18432: 16-row stride per cp group

// ---------------- scratch (device globals) ----------------
__device__ __nv_bfloat16 g_Qh[(size_t)QF * DD];
__device__ __nv_bfloat16 g_Sh[(size_t)SF * DD];
__device__ float g_qn[QF];
__device__ float g_sn[SF];

// ---------------- PTX helpers ----------------
__device__ __forceinline__ uint32_t smem_u32(const void* p) {
    uint32_t a;
    asm("{ .reg .u64 t; cvta.to.shared.u64 t, %1; cvt.u32.u64 %0, t; }"
        : "=r"(a) : "l"(p));
    return a;
}
__device__ __forceinline__ void cp16(uint32_t saddr, const void* gptr) {
    asm volatile("cp.async.cg.shared.global [%0], [%1], 16;"
                 :: "r"(saddr), "l"(gptr) : "memory");
}
#define CP_COMMIT() asm volatile("cp.async.commit_group;" ::: "memory")
#define CP_WAIT(n)  asm volatile("cp.async.wait_group %0;" :: "n"(n) : "memory")

__device__ __forceinline__ uint32_t pack_bf16x2(float lo, float hi) {
    uint32_t r;
    asm("cvt.rn.bf16x2.f32 %0, %1, %2;" : "=r"(r) : "f"(hi), "f"(lo));
    return r;
}
__device__ __forceinline__ void ldsm4(uint32_t r[4], uint32_t addr) {
    asm volatile("ldmatrix.sync.aligned.m8n8.x4.shared.b16 {%0,%1,%2,%3}, [%4];"
                 : "=r"(r[0]), "=r"(r[1]), "=r"(r[2]), "=r"(r[3]) : "r"(addr));
}
__device__ __forceinline__ void mma16816(float c[4], const uint32_t a[4],
                                         uint32_t b0, uint32_t b1) {
    asm volatile(
        "mma.sync.aligned.m16n8k16.row.col.f32.bf16.bf16.f32 "
        "{%0,%1,%2,%3}, {%4,%5,%6,%7}, {%8,%9}, {%0,%1,%2,%3};"
        : "+f"(c[0]), "+f"(c[1]), "+f"(c[2]), "+f"(c[3])
        : "r"(a[0]), "r"(a[1]), "r"(a[2]), "r"(a[3]), "r"(b0), "r"(b1));
}
__device__ __forceinline__ uint32_t sw128(uint32_t off) {
    return off ^ ((off >> 3) & 0x70);
}
__device__ __forceinline__ float ex2f(float x) {
    float y; asm("ex2.approx.ftz.f32 %0, %1;" : "=f"(y) : "f"(x)); return y;
}
__device__ __forceinline__ float lg2f(float x) {
    float y; asm("lg2.approx.ftz.f32 %0, %1;" : "=f"(y) : "f"(x)); return y;
}

// ================= convert (f32 -> bf16) + norms =================
__global__ __launch_bounds__(256) void convert_kernel(const float* __restrict__ Q,
                                                      const float* __restrict__ S) {
    int w = (blockIdx.x * blockDim.x + threadIdx.x) >> 5;
    int lane = threadIdx.x & 31;
    if (w >= QF + SF) return;
    bool isQ = (w < QF);
    int r = isQ ? w : (w - QF);
    const float4* src = (const float4*)((isQ ? Q : S) + (size_t)r * DD);  // 144/row
    uint2* dst = (uint2*)((isQ ? g_Qh : g_Sh) + (size_t)r * DD);
    float s = 0.f;
#pragma unroll
    for (int j = 0; j < 4; j++) {
        int k = lane + 32 * j;
        float4 v = src[k];
        s = fmaf(v.x, v.x, fmaf(v.y, v.y, fmaf(v.z, v.z, fmaf(v.w, v.w, s))));
        uint2 o;
        o.x = pack_bf16x2(v.x, v.y);
        o.y = pack_bf16x2(v.z, v.w);
        dst[k] = o;
    }
    if (lane < 16) {
        int k = 128 + lane;
        float4 v = src[k];
        s = fmaf(v.x, v.x, fmaf(v.y, v.y, fmaf(v.z, v.z, fmaf(v.w, v.w, s))));
        uint2 o;
        o.x = pack_bf16x2(v.x, v.y);
        o.y = pack_bf16x2(v.z, v.w);
        dst[k] = o;
    }
#pragma unroll
    for (int o = 16; o > 0; o >>= 1) s += __shfl_down_sync(0xffffffffu, s, o);
    if (lane == 0) {
        float n = sqrtf(s);
        if (isQ) g_qn[r] = n;
        else     g_sn[r] = n;
    }
}

// ================= softmins (lbda = 0.5) =================
#define CEXP 2.885390081777927f   // 2/ln2
#define CLOG 0.346573590279973f   // 0.5*ln2
__device__ __forceinline__ float softmin2(float a, float b) {
    float m = fminf(a, b), x = fmaxf(a, b);
    float s = 1.f + ex2f(CEXP * (m - x));
    return fmaf(-CLOG, lg2f(s), m);
}
__device__ __forceinline__ float softmin3(float a, float b, float c) {
    float m = fminf(fminf(a, b), c);
    float x = fmaxf(fmaxf(a, b), c);
    float mid = ((a + b) + c) - m - x;
    float s = 1.f + ex2f(CEXP * (m - mid)) + ex2f(CEXP * (m - x));
    return fmaf(-CLOG, lg2f(s), m);
}

// ================= fused GEMM + epilogue + DP =================
struct Frags { uint32_t a[4][4]; uint32_t b[2][4]; };   // 24 regs

__device__ __forceinline__ void load_frags(Frags& f, uint32_t Ab, uint32_t Bb,
                                           int ks, int wm, int wn, int lane) {
#pragma unroll
    for (int fm = 0; fm < 4; fm++) {
        int row = wm * 64 + fm * 16 + (lane & 15);
        uint32_t off = row * 128 + ks * 32 + ((lane >> 4) & 1) * 16;
        ldsm4(f.a[fm], Ab + sw128(off));
    }
#pragma unroll
    for (int p = 0; p < 2; p++) {
        int n = wn * 32 + p * 16 + (lane & 7) + ((lane >> 4) & 1) * 8;
        uint32_t off = n * 128 + ks * 32 + ((lane >> 3) & 1) * 16;
        ldsm4(f.b[p], Bb + sw128(off));
    }
}
__device__ __forceinline__ void mma_frags(float acc[4][4][4], const Frags& f) {
#pragma unroll
    for (int fm = 0; fm < 4; fm++) {
        mma16816(acc[fm][0], f.a[fm], f.b[0][0], f.b[0][1]);
        mma16816(acc[fm][1], f.a[fm], f.b[0][2], f.b[0][3]);
        mma16816(acc[fm][2], f.a[fm], f.b[1][0], f.b[1][1]);
        mma16816(acc[fm][3], f.a[fm], f.b[1][2], f.b[1][3]);
    }
}

// Affine loader: per thread, row = (tid>>3) + 16i, 16B-slot v = tid&7.
// sw128 touches only bits [6:4]; the +2048*i term (bits >= 11) commutes
// with it, so dst = base_off + 2048*i and src = base_ptr + 18432*i.
__device__ __forceinline__ void issue_chunk(uint32_t stgStage,
                                            const char* aSrc, const char* bSrc,
                                            uint32_t dOff) {
#pragma unroll
    for (int i = 0; i < 8; i++)
        cp16(stgStage + dOff + 2048u * i, aSrc + (size_t)LDSTRIDE * i);
#pragma unroll
    for (int i = 0; i < 4; i++)
        cp16(stgStage + A_STAGE + dOff + 2048u * i, bSrc + (size_t)LDSTRIDE * i);
    CP_COMMIT();
}

__global__ __launch_bounds__(NTHREADS, 4) void fused_kernel(float* __restrict__ out) {
    extern __shared__ char smem[];
    const uint32_t sb = smem_u32(smem);
    float* sqn = (float*)smem;            // [128]
    float* ssn = (float*)(smem + 512);    // [64]
    const uint32_t stg = sb + SMEM_NORMS;
    const int tid = threadIdx.x;
    const int wid = tid >> 5;
    const int lane = tid & 31;
    const int bcol = blockIdx.x * N_TILE;
    const int brow = blockIdx.y * M_TILE;

    if (tid < 128) sqn[tid] = g_qn[brow + tid];
    if (tid < 64)  ssn[tid] = g_sn[bcol + tid];

    // per-thread affine loader bases
    const uint32_t ldRow = tid >> 3, ldV = (tid & 7) * 16;
    const char* aSrc = (const char*)(g_Qh + (size_t)brow * DD) +
                       (size_t)ldRow * ROWB + ldV;
    const char* bSrc = (const char*)(g_Sh + (size_t)bcol * DD) +
                       (size_t)ldRow * ROWB + ldV;
    const uint32_t dOff = sw128(ldRow * 128 + ldV);

    const int wm = wid & 1;    // 2 m-groups of 64 rows
    const int wn = wid >> 1;   // 2 n-groups of 32 cols

    float acc[4][4][4];
#pragma unroll
    for (int i = 0; i < 4; i++)
#pragma unroll
        for (int j = 0; j < 4; j++)
#pragma unroll
            for (int k = 0; k < 4; k++) acc[i][j][k] = 0.f;

    issue_chunk(stg, aSrc, bSrc, dOff);

    Frags fr[2];
#pragma unroll 1
    for (int c = 0; c < NCHUNK; c++) {
        CP_WAIT(0);                          // chunk c landed (this thread)
        __syncthreads();                     // published; s^1 readers done
        if (c + 1 < NCHUNK)
            issue_chunk(stg + ((c + 1) & 1) * STAGE_BYTES,
                        aSrc + (size_t)(c + 1) * (KC * 2),
                        bSrc + (size_t)(c + 1) * (KC * 2), dOff);
        const int s = c & 1;
        const uint32_t Ab = stg + s * STAGE_BYTES;
        const uint32_t Bb = Ab + A_STAGE;
        load_frags(fr[0], Ab, Bb, 0, wm, wn, lane);
#pragma unroll
        for (int ks = 0; ks < 4; ks++) {     // double-buffered fragments
            if (ks < 3) load_frags(fr[(ks + 1) & 1], Ab, Bb, ks + 1, wm, wn, lane);
            mma_frags(acc, fr[ks & 1]);
        }
    }
    __syncthreads();   // all stage reads done before dist overlay

    // ---- epilogue: normalized dists into smem [128][DSTRIDE] ----
    float* sdist = (float*)(smem + SMEM_NORMS);
    const int gid = lane >> 2;
    const int tc  = (lane & 3) * 2;
#pragma unroll
    for (int fm = 0; fm < 4; fm++) {
        int r0 = wm * 64 + fm * 16 + gid;
        float qn0 = sqn[r0], qn1 = sqn[r0 + 8];
#pragma unroll
        for (int fn = 0; fn < 4; fn++) {
            int c0 = wn * 32 + fn * 8 + tc;
            float sn0 = ssn[c0], sn1 = ssn[c0 + 1];
            float* a = acc[fm][fn];
            float2 v0 = make_float2(1.f - __fdividef(a[0], fmaf(qn0, sn0, EPSILON)),
                                    1.f - __fdividef(a[1], fmaf(qn0, sn1, EPSILON)));
            float2 v1 = make_float2(1.f - __fdividef(a[2], fmaf(qn1, sn0, EPSILON)),
                                    1.f - __fdividef(a[3], fmaf(qn1, sn1, EPSILON)));
            *(float2*)&sdist[r0 * DSTRIDE + c0] = v0;
            *(float2*)&sdist[(r0 + 8) * DSTRIDE + c0] = v1;
        }
    }
    __syncthreads();

    // ---- OTAM DP: 128 pairs, one thread each; forward + loop-exchanged
    // transposed DP merged in one streaming pass over the 8 dist rows ----
    {
        const int ql = tid >> 3;
        const int cl = tid & 7;
        const float* base = sdist + (ql * 8) * DSTRIDE + cl * 8;

        float F[10];   // forward DP front
        float T[8];    // transposed DP front

        float r0[8];
        {
            float4 u = *(const float4*)base;
            float4 w = *(const float4*)(base + 4);
            r0[0] = u.x; r0[1] = u.y; r0[2] = u.z; r0[3] = u.w;
            r0[4] = w.x; r0[5] = w.y; r0[6] = w.z; r0[7] = w.w;
        }
        float run = 0.f;
#pragma unroll
        for (int m = 1; m <= 8; m++) { run += r0[m - 1]; F[m] = run; }
        F[9] = run;
        T[0] = r0[0];
#pragma unroll
        for (int l = 1; l < 8; l++)
            T[l] = r0[l] + softmin3(0.f, 0.f, T[l - 1]);

#pragma unroll
        for (int j = 1; j < 8; j++) {
            float r[8];
            const float* rp = base + j * DSTRIDE;
            float4 u = *(const float4*)rp;
            float4 w = *(const float4*)(rp + 4);
            r[0] = u.x; r[1] = u.y; r[2] = u.z; r[3] = u.w;
            r[4] = w.x; r[5] = w.y; r[6] = w.z; r[7] = w.w;
            // forward row step
            float diag, left;
            {
                float nf = r[0] + softmin3(0.f, 0.f, F[1]);
                diag = F[1]; F[1] = nf; left = nf;
            }
#pragma unroll
            for (int m = 2; m <= 8; m++) {
                float nf = r[m - 1] + softmin2(diag, left);
                diag = F[m]; F[m] = nf; left = nf;
            }
            F[9] = softmin3(diag, left, F[9]);
            // transposed column step (outer index m = j+1)
            float prev_old = T[0];
            T[0] += r[0];
#pragma unroll
            for (int l = 1; l < 8; l++) {
                float cur_old = T[l];
                T[l] = r[l] + softmin2(prev_old, cur_old);
                prev_old = cur_old;
            }
        }
        {   // transposed pad step (m = 9, e = 0, include_up)
            float prev_old = T[0];
#pragma unroll
            for (int l = 1; l < 8; l++) {
                float cur_old = T[l];
                T[l] = softmin3(prev_old, cur_old, T[l - 1]);
                prev_old = cur_old;
            }
        }
        out[(blockIdx.y * 16 + ql) * NS + (blockIdx.x * 8 + cl)] = -(F[9] + T[7]);
    }
}

// ================= launch =================
extern "C" void kernel_launch(void* const* d_in, const int* in_sizes, int n_in,
                              void* d_out, int out_size) {
    const float* sup = (const float*)d_in[0];
    const float* qry = (const float*)d_in[1];
    if (n_in >= 2 && in_sizes[0] > in_sizes[1]) {
        const float* t = sup; sup = qry; qry = t;
    }
    float* out = (float*)d_out;

    {
        int warps = QF + SF;                    // 16896
        convert_kernel<<<(warps + 7) / 8, 256>>>(qry, sup);
    }
    {
        cudaFuncSetAttribute(fused_kernel,
                             cudaFuncAttributeMaxDynamicSharedMemorySize, SMEM_TOTAL);
        dim3 grid(SF / N_TILE, QF / M_TILE);    // (8, 128)
        fused_kernel<<<grid, NTHREADS, SMEM_TOTAL>>>(out);
    }
}

// round 17
// speedup vs baseline: 1.2571x; 1.0406x over previous
#include <cuda_runtime.h>
#include <cuda_bf16.h>
#include <math.h>
#include <stdint.h>

// ---------------- problem shapes ----------------
#define NQ 2048
#define NS 64
#define LL 8
#define DD 576
#define QF (NQ * LL)   // 16384 query frames
#define SF (NS * LL)   // 512 support frames
#define EPSILON 0.01f

// ---------------- GEMM tiling (R14/R16 config) ----------------
#define M_TILE 128
#define N_TILE 64
#define KC 64                                // bf16 K-elems per chunk: 128B rows
#define NCHUNK (DD / KC)                     // 9
#define A_STAGE (M_TILE * 128)               // 16384
#define B_STAGE (N_TILE * 128)               // 8192
#define STAGE_BYTES (A_STAGE + B_STAGE)      // 24576
#define SMEM_NORMS 1024
#define DSTRIDE 68                           // dist row stride (floats, 16B-aligned)
#define SMEM_TOTAL (SMEM_NORMS + 2 * STAGE_BYTES)  // 50176; x4 CTAs = 200704

#define NTHREADS 128                         // 4 warps, each 64x32 warp tile
#define ROWB (DD * 2)                        // 1152 bytes per gmem row
#define LDSTRIDE (16 * ROWB)                 // 18432: 16-row stride per cp group

// ---------------- scratch (device globals) ----------------
__device__ __nv_bfloat16 g_Qh[(size_t)QF * DD];
__device__ __nv_bfloat16 g_Sh[(size_t)SF * DD];
__device__ float g_qn[QF];   // RECIPROCAL query-frame norms
__device__ float g_sn[SF];   // RECIPROCAL support-frame norms

// ---------------- PTX helpers ----------------
__device__ __forceinline__ uint32_t smem_u32(const void* p) {
    uint32_t a;
    asm("{ .reg .u64 t; cvta.to.shared.u64 t, %1; cvt.u32.u64 %0, t; }"
        : "=r"(a) : "l"(p));
    return a;
}
__device__ __forceinline__ void cp16(uint32_t saddr, const void* gptr) {
    asm volatile("cp.async.cg.shared.global [%0], [%1], 16;"
                 :: "r"(saddr), "l"(gptr) : "memory");
}
#define CP_COMMIT() asm volatile("cp.async.commit_group;" ::: "memory")
#define CP_WAIT(n)  asm volatile("cp.async.wait_group %0;" :: "n"(n) : "memory")

__device__ __forceinline__ uint32_t pack_bf16x2(float lo, float hi) {
    uint32_t r;
    asm("cvt.rn.bf16x2.f32 %0, %1, %2;" : "=r"(r) : "f"(hi), "f"(lo));
    return r;
}
__device__ __forceinline__ void ldsm4(uint32_t r[4], uint32_t addr) {
    asm volatile("ldmatrix.sync.aligned.m8n8.x4.shared.b16 {%0,%1,%2,%3}, [%4];"
                 : "=r"(r[0]), "=r"(r[1]), "=r"(r[2]), "=r"(r[3]) : "r"(addr));
}
__device__ __forceinline__ void mma16816(float c[4], const uint32_t a[4],
                                         uint32_t b0, uint32_t b1) {
    asm volatile(
        "mma.sync.aligned.m16n8k16.row.col.f32.bf16.bf16.f32 "
        "{%0,%1,%2,%3}, {%4,%5,%6,%7}, {%8,%9}, {%0,%1,%2,%3};"
        : "+f"(c[0]), "+f"(c[1]), "+f"(c[2]), "+f"(c[3])
        : "r"(a[0]), "r"(a[1]), "r"(a[2]), "r"(a[3]), "r"(b0), "r"(b1));
}
__device__ __forceinline__ uint32_t sw128(uint32_t off) {
    return off ^ ((off >> 3) & 0x70);
}
__device__ __forceinline__ float ex2f(float x) {
    float y; asm("ex2.approx.ftz.f32 %0, %1;" : "=f"(y) : "f"(x)); return y;
}
__device__ __forceinline__ float lg2f(float x) {
    float y; asm("lg2.approx.ftz.f32 %0, %1;" : "=f"(y) : "f"(x)); return y;
}

// softmin constants (lbda = 0.5):  e^{-2d} = 2^{-CEXP*d},  0.5*ln2 = CLOG
#define CEXP 2.885390081777927f   // 2/ln2
#define CLOG 0.346573590279973f   // 0.5*ln2

// ================= convert (f32 -> bf16) + reciprocal norms =================
__global__ __launch_bounds__(256) void convert_kernel(const float* __restrict__ Q,
                                                      const float* __restrict__ S) {
    int w = (blockIdx.x * blockDim.x + threadIdx.x) >> 5;
    int lane = threadIdx.x & 31;
    if (w >= QF + SF) return;
    bool isQ = (w < QF);
    int r = isQ ? w : (w - QF);
    const float4* src = (const float4*)((isQ ? Q : S) + (size_t)r * DD);  // 144/row
    uint2* dst = (uint2*)((isQ ? g_Qh : g_Sh) + (size_t)r * DD);
    float s = 0.f;
#pragma unroll
    for (int j = 0; j < 4; j++) {
        int k = lane + 32 * j;
        float4 v = src[k];
        s = fmaf(v.x, v.x, fmaf(v.y, v.y, fmaf(v.z, v.z, fmaf(v.w, v.w, s))));
        uint2 o;
        o.x = pack_bf16x2(v.x, v.y);
        o.y = pack_bf16x2(v.z, v.w);
        dst[k] = o;
    }
    if (lane < 16) {
        int k = 128 + lane;
        float4 v = src[k];
        s = fmaf(v.x, v.x, fmaf(v.y, v.y, fmaf(v.z, v.z, fmaf(v.w, v.w, s))));
        uint2 o;
        o.x = pack_bf16x2(v.x, v.y);
        o.y = pack_bf16x2(v.z, v.w);
        dst[k] = o;
    }
#pragma unroll
    for (int o = 16; o > 0; o >>= 1) s += __shfl_down_sync(0xffffffffu, s, o);
    if (lane == 0) {
        float rn = rsqrtf(s);               // 1/||row||
        if (isQ) g_qn[r] = rn;
        else     g_sn[r] = rn;
    }
}

// ================= fused GEMM + epilogue + exponential-domain DP ===========
struct Frags { uint32_t a[4][4]; uint32_t b[2][4]; };   // 24 regs

__device__ __forceinline__ void load_frags(Frags& f, uint32_t Ab, uint32_t Bb,
                                           int ks, int wm, int wn, int lane) {
#pragma unroll
    for (int fm = 0; fm < 4; fm++) {
        int row = wm * 64 + fm * 16 + (lane & 15);
        uint32_t off = row * 128 + ks * 32 + ((lane >> 4) & 1) * 16;
        ldsm4(f.a[fm], Ab + sw128(off));
    }
#pragma unroll
    for (int p = 0; p < 2; p++) {
        int n = wn * 32 + p * 16 + (lane & 7) + ((lane >> 4) & 1) * 8;
        uint32_t off = n * 128 + ks * 32 + ((lane >> 3) & 1) * 16;
        ldsm4(f.b[p], Bb + sw128(off));
    }
}
__device__ __forceinline__ void mma_frags(float acc[4][4][4], const Frags& f) {
#pragma unroll
    for (int fm = 0; fm < 4; fm++) {
        mma16816(acc[fm][0], f.a[fm], f.b[0][0], f.b[0][1]);
        mma16816(acc[fm][1], f.a[fm], f.b[0][2], f.b[0][3]);
        mma16816(acc[fm][2], f.a[fm], f.b[1][0], f.b[1][1]);
        mma16816(acc[fm][3], f.a[fm], f.b[1][2], f.b[1][3]);
    }
}

// Affine loader (R16): sw128 commutes with +2048*i.
__device__ __forceinline__ void issue_chunk(uint32_t stgStage,
                                            const char* aSrc, const char* bSrc,
                                            uint32_t dOff) {
#pragma unroll
    for (int i = 0; i < 8; i++)
        cp16(stgStage + dOff + 2048u * i, aSrc + (size_t)LDSTRIDE * i);
#pragma unroll
    for (int i = 0; i < 4; i++)
        cp16(stgStage + A_STAGE + dOff + 2048u * i, bSrc + (size_t)LDSTRIDE * i);
    CP_COMMIT();
}

// Epilogue per element: d = 1 - dot/(qn*sn+eps); store W = e^{-2d}.
// 1/(qn*sn+eps) = r*(1 - eps*r + (eps*r)^2), r = rq*rs  (eps*r ~ 1.7e-5).
__device__ __forceinline__ float wexp(float dot, float rq, float rs) {
    float r = rq * rs;
    float t = EPSILON * r;
    float corr = fmaf(t, t, 1.f) - t;
    float p = CEXP * (r * corr);
    return ex2f(fmaf(p, dot, -CEXP));       // 2^{CEXP*(dot*rc - 1)}
}

__global__ __launch_bounds__(NTHREADS, 4) void fused_kernel(float* __restrict__ out) {
    extern __shared__ char smem[];
    const uint32_t sb = smem_u32(smem);
    float* sqn = (float*)smem;            // [128] reciprocal q norms
    float* ssn = (float*)(smem + 512);    // [64]  reciprocal s norms
    const uint32_t stg = sb + SMEM_NORMS;
    const int tid = threadIdx.x;
    const int wid = tid >> 5;
    const int lane = tid & 31;
    const int bcol = blockIdx.x * N_TILE;
    const int brow = blockIdx.y * M_TILE;

    if (tid < 128) sqn[tid] = g_qn[brow + tid];
    if (tid < 64)  ssn[tid] = g_sn[bcol + tid];

    // per-thread affine loader bases
    const uint32_t ldRow = tid >> 3, ldV = (tid & 7) * 16;
    const char* aSrc = (const char*)(g_Qh + (size_t)brow * DD) +
                       (size_t)ldRow * ROWB + ldV;
    const char* bSrc = (const char*)(g_Sh + (size_t)bcol * DD) +
                       (size_t)ldRow * ROWB + ldV;
    const uint32_t dOff = sw128(ldRow * 128 + ldV);

    const int wm = wid & 1;    // 2 m-groups of 64 rows
    const int wn = wid >> 1;   // 2 n-groups of 32 cols

    float acc[4][4][4];
#pragma unroll
    for (int i = 0; i < 4; i++)
#pragma unroll
        for (int j = 0; j < 4; j++)
#pragma unroll
            for (int k = 0; k < 4; k++) acc[i][j][k] = 0.f;

    issue_chunk(stg, aSrc, bSrc, dOff);

    Frags fr[2];
#pragma unroll 1
    for (int c = 0; c < NCHUNK; c++) {
        CP_WAIT(0);                          // chunk c landed (this thread)
        __syncthreads();                     // published; s^1 readers done
        if (c + 1 < NCHUNK)
            issue_chunk(stg + ((c + 1) & 1) * STAGE_BYTES,
                        aSrc + (size_t)(c + 1) * (KC * 2),
                        bSrc + (size_t)(c + 1) * (KC * 2), dOff);
        const int s = c & 1;
        const uint32_t Ab = stg + s * STAGE_BYTES;
        const uint32_t Bb = Ab + A_STAGE;
        load_frags(fr[0], Ab, Bb, 0, wm, wn, lane);
#pragma unroll
        for (int ks = 0; ks < 4; ks++) {     // double-buffered fragments
            if (ks < 3) load_frags(fr[(ks + 1) & 1], Ab, Bb, ks + 1, wm, wn, lane);
            mma_frags(acc, fr[ks & 1]);
        }
    }
    __syncthreads();   // all stage reads done before dist overlay

    // ---- epilogue: W = e^{-2*dist} into smem [128][DSTRIDE] ----
    float* sdist = (float*)(smem + SMEM_NORMS);
    const int gid = lane >> 2;
    const int tc  = (lane & 3) * 2;
#pragma unroll
    for (int fm = 0; fm < 4; fm++) {
        int r0 = wm * 64 + fm * 16 + gid;
        float rq0 = sqn[r0], rq1 = sqn[r0 + 8];
#pragma unroll
        for (int fn = 0; fn < 4; fn++) {
            int c0 = wn * 32 + fn * 8 + tc;
            float rs0 = ssn[c0], rs1 = ssn[c0 + 1];
            float* a = acc[fm][fn];
            float2 v0 = make_float2(wexp(a[0], rq0, rs0), wexp(a[1], rq0, rs1));
            float2 v1 = make_float2(wexp(a[2], rq1, rs0), wexp(a[3], rq1, rs1));
            *(float2*)&sdist[r0 * DSTRIDE + c0] = v0;
            *(float2*)&sdist[(r0 + 8) * DSTRIDE + c0] = v1;
        }
    }
    __syncthreads();

    // ---- OTAM DP in the EXPONENTIAL domain: softmin -> mul/add.
    // E = e^{-2*cum}; cum = d + softmin(a,b)  <=>  E = W*(Ea+Eb).
    // One thread per pair; forward + loop-exchanged transposed DP share rows.
    {
        const int ql = tid >> 3;
        const int cl = tid & 7;
        const float* base = sdist + (ql * 8) * DSTRIDE + cl * 8;

        float EF[10];   // forward front (EF[0] == 1 implicit)
        float ET[8];    // transposed front

        float r0[8];
        {
            float4 u = *(const float4*)base;
            float4 w = *(const float4*)(base + 4);
            r0[0] = u.x; r0[1] = u.y; r0[2] = u.z; r0[3] = u.w;
            r0[4] = w.x; r0[5] = w.y; r0[6] = w.z; r0[7] = w.w;
        }
        // forward row 0: cumsum -> running product
        float e = 1.f;
#pragma unroll
        for (int m = 1; m <= 8; m++) { e *= r0[m - 1]; EF[m] = e; }
        EF[9] = e;
        // transposed m=1 column
        ET[0] = r0[0];
#pragma unroll
        for (int l = 1; l < 8; l++)
            ET[l] = r0[l] * (2.f + ET[l - 1]);   // softmin3(0,0,T[l-1])

#pragma unroll
        for (int j = 1; j < 8; j++) {
            float r[8];
            const float* rp = base + j * DSTRIDE;
            float4 u = *(const float4*)rp;
            float4 w = *(const float4*)(rp + 4);
            r[0] = u.x; r[1] = u.y; r[2] = u.z; r[3] = u.w;
            r[4] = w.x; r[5] = w.y; r[6] = w.z; r[7] = w.w;
            // forward row step
            float diag, left;
            {
                float nf = r[0] * (2.f + EF[1]);   // softmin3(prev0=0, cur0=0, prev1)
                diag = EF[1]; EF[1] = nf; left = nf;
            }
#pragma unroll
            for (int m = 2; m <= 8; m++) {
                float nf = r[m - 1] * (diag + left);
                diag = EF[m]; EF[m] = nf; left = nf;
            }
            EF[9] = diag + left + EF[9];           // pad col (d=0, include_up)
            // transposed column step (outer index m = j+1)
            float prev_old = ET[0];
            ET[0] *= r[0];
#pragma unroll
            for (int l = 1; l < 8; l++) {
                float cur_old = ET[l];
                ET[l] = r[l] * (prev_old + cur_old);
                prev_old = cur_old;
            }
        }
        {   // transposed pad step (m = 9, d = 0, include_up)
            float prev_old = ET[0];
#pragma unroll
            for (int l = 1; l < 8; l++) {
                float cur_old = ET[l];
                ET[l] = prev_old + cur_old + ET[l - 1];
                prev_old = cur_old;
            }
        }
        // out = -(F + T) = CLOG*(lg2(EF9) + lg2(ET7))
        out[(blockIdx.y * 16 + ql) * NS + (blockIdx.x * 8 + cl)] =
            CLOG * (lg2f(EF[9]) + lg2f(ET[7]));
    }
}

// ================= launch =================
extern "C" void kernel_launch(void* const* d_in, const int* in_sizes, int n_in,
                              void* d_out, int out_size) {
    const float* sup = (const float*)d_in[0];
    const float* qry = (const float*)d_in[1];
    if (n_in >= 2 && in_sizes[0] > in_sizes[1]) {
        const float* t = sup; sup = qry; qry = t;
    }
    float* out = (float*)d_out;

    {
        int warps = QF + SF;                    // 16896
        convert_kernel<<<(warps + 7) / 8, 256>>>(qry, sup);
    }
    {
        cudaFuncSetAttribute(fused_kernel,
                             cudaFuncAttributeMaxDynamicSharedMemorySize, SMEM_TOTAL);
        dim3 grid(SF / N_TILE, QF / M_TILE);    // (8, 128)
        fused_kernel<<<grid, NTHREADS, SMEM_TOTAL>>>(out);
    }
}